// round 9
// baseline (speedup 1.0000x reference)
#include <cuda_runtime.h>
#include <cuda_fp16.h>

// 5x5 median blur, zero padding, [N, 512, 512] fp32 planes (N = 24).
//
// fp16x2-packed compare-exchange network; each half2 lane pair carries two
// horizontally adjacent-window pixels (p, p+2). All min/max are EXACT
// (HMNMX2), so every output equals some fp16-converted input (rel err <=
// 2^-11 for normal values). Tiny medians (fp16 subnormal zone) are
// recomputed in fp32 under a rare predicate.
//
// NEW (R9): each thread computes TWO output rows (y, y+1). Their 5-row
// column windows share rows y-1..y+2, so per column we do one sort4 of the
// shared quad (5 CE) plus a 4-CE insertion per window: 13 CE per 2 rows
// instead of 18 -- column-sort cost drops ~46%.
//
// Selection pipeline (proved in earlier rounds, verified on-device):
//  both-sorted rank bound -> 13 candidates -> chain merges -> pruned
//  Batcher merge(5,5) -> median7 -> chain med5 formula.

__device__ __align__(16) float g_zeros[544];  // zero-initialized, never written

__device__ __forceinline__ float   vmn(float a, float b)     { return fminf(a, b); }
__device__ __forceinline__ float   vmx(float a, float b)     { return fmaxf(a, b); }
__device__ __forceinline__ __half2 vmn(__half2 a, __half2 b) { return __hmin2(a, b); }
__device__ __forceinline__ __half2 vmx(__half2 a, __half2 b) { return __hmax2(a, b); }

template <class T>
__device__ __forceinline__ void ce(T& a, T& b) {
    T t = vmn(a, b);
    b = vmx(a, b);
    a = t;
}

template <class T>
__device__ __forceinline__ void sort5(T& s0, T& s1, T& s2, T& s3, T& s4) {
    ce(s0, s1); ce(s2, s3); ce(s0, s2); ce(s1, s3); ce(s1, s2);
    ce(s3, s4); ce(s2, s3); ce(s1, s2); ce(s0, s1);
}

// sort4 (5 CE)
template <class T>
__device__ __forceinline__ void sort4(T& s1, T& s2, T& s3, T& s4) {
    ce(s1, s2); ce(s3, s4); ce(s1, s3); ce(s2, s4); ce(s2, s3);
}

// insert e into ascending (s1<=s2<=s3<=s4) -> o[0..4] sorted (4 CE, non-destructive)
template <class T>
__device__ __forceinline__ void insert5(T* o, T e, T s1, T s2, T s3, T s4) {
    T t = e;
    o[0] = vmn(t, s1); t = vmx(t, s1);
    o[1] = vmn(t, s2); t = vmx(t, s2);
    o[2] = vmn(t, s3); t = vmx(t, s3);
    o[3] = vmn(t, s4); o[4] = vmx(t, s4);
}

// sort5 minus final CE(s0,s1): ranks 2,3,4 correct in s2,s3,s4 (8 CE)
template <class T>
__device__ __forceinline__ void sort5_hi(T& s0, T& s1, T& s2, T& s3, T& s4) {
    ce(s0, s1); ce(s2, s3); ce(s0, s2); ce(s1, s3); ce(s1, s2);
    ce(s3, s4); ce(s2, s3); ce(s1, s2);
}

// reflected sort5 minus final CE(s3,s4): ranks 0,1,2 correct in s0,s1,s2 (8 CE)
template <class T>
__device__ __forceinline__ void sort5_lo(T& s0, T& s1, T& s2, T& s3, T& s4) {
    ce(s3, s4); ce(s1, s2); ce(s2, s4); ce(s1, s3); ce(s2, s3);
    ce(s0, s1); ce(s1, s2); ce(s2, s3);
}

// non-destructive top-2 of 5 (sorted): snd = rank3, mxv = rank4
template <class T>
__device__ __forceinline__ void top2(T e0, T e1, T e2, T e3, T e4, T& snd, T& mxv) {
    T u1 = vmx(e0, e1), l1 = vmn(e0, e1);
    T u2 = vmx(e2, e3), l2 = vmn(e2, e3);
    T M4 = vmx(u1, u2);
    T S4 = vmx(vmn(u1, u2), vmx(l1, l2));
    mxv = vmx(M4, e4);
    snd = vmx(vmn(M4, e4), S4);
}

// non-destructive bottom-2 of 5 (sorted): mnv = rank0, snd = rank1
template <class T>
__device__ __forceinline__ void bot2(T e0, T e1, T e2, T e3, T e4, T& mnv, T& snd) {
    T l1 = vmn(e0, e1), u1 = vmx(e0, e1);
    T l2 = vmn(e2, e3), u2 = vmx(e2, e3);
    T m4 = vmn(l1, l2);
    T s4 = vmn(vmx(l1, l2), vmn(u1, u2));
    mnv = vmn(m4, e4);
    snd = vmn(vmx(m4, e4), s4);
}

// Median-of-25 given 5 ascending-sorted columns c0..c4 (each 5 elements).
template <class T>
__device__ __forceinline__ T median25_cols(const T* c0, const T* c1, const T* c2,
                                           const T* c3, const T* c4) {
    T A, Bv, L, Mv;
    top2(c0[0], c1[0], c2[0], c3[0], c4[0], A, Bv);   // row0 ranks 3,4
    bot2(c0[4], c1[4], c2[4], c3[4], c4[4], L, Mv);   // row4 ranks 0,1

    T a0 = c0[1], a1 = c1[1], a2 = c2[1], a3 = c3[1], a4 = c4[1];
    sort5_hi(a0, a1, a2, a3, a4);
    T C = a2, D = a3, E = a4;                          // row1 ranks 2,3,4
    T b0 = c0[2], b1 = c1[2], b2 = c2[2], b3 = c3[2], b4 = c4[2];
    sort5(b0, b1, b2, b3, b4);
    T F = b1, G = b2, Hh = b3;                         // row2 ranks 1,2,3
    T u0 = c0[3], u1 = c1[3], u2 = c2[3], u3 = c3[3], u4 = c4[3];
    sort5_lo(u0, u1, u2, u3, u4);
    T I = u0, J = u1, K = u2;                          // row3 ranks 0,1,2

    // chain merges -> sorted 5-chains Z=(A,D,Hh,Bv,E), X=(F,L,I,J,Mv)
    ce(D, Bv); ce(Hh, Bv); ce(Bv, E);
    ce(F, I);  ce(L, I);   ce(I, J);

    // pruned Batcher merge(5,5): middle four w3..w6 in e2,p2,e3,q2
    T p1 = vmx(F, A);
    T q1 = vmn(Mv, E);
    ce(p1, q1);
    ce(I, Hh);
    T e2 = vmx(p1, I);
    T e3 = vmn(q1, Hh);
    T p2 = vmx(L, D);
    T q2 = vmn(J, Bv);
    ce(p2, q2);
    ce(e2, p2);
    ce(e3, q2);

    // median13 = rank3 of {w3,w4,w5,w6, C,G,K}
    T t0 = vmx(e2, C);
    T t1 = vmn(q2, K);
    T t2 = G;
    ce(t0, t1); ce(t0, t2); ce(t1, t2);
    T m1 = vmx(p2, t0);
    T m2 = vmn(e3, t2);
    T lo = vmn(m1, m2), hi = vmx(m1, m2);
    return vmx(lo, vmn(hi, t1));
}

// Rare fp32 recompute for medians in the fp16 subnormal zone.
__device__ __noinline__ float median25_fixup(const float* __restrict__ base, int px, int py) {
    float c[5][5];
#pragma unroll
    for (int i = 0; i < 5; i++) {
        const int x = px - 2 + i;
        const bool xin = (unsigned)x < 512u;
#pragma unroll
        for (int r = 0; r < 5; r++) {
            const int yy = py - 2 + r;
            const bool in = xin && ((unsigned)yy < 512u);
            c[i][r] = in ? __ldg(base + (size_t)yy * 512 + x) : 0.0f;
        }
        sort5(c[i][0], c[i][1], c[i][2], c[i][3], c[i][4]);
    }
    return median25_cols(c[0], c[1], c[2], c[3], c[4]);
}

__global__ __launch_bounds__(128) void MedianBlur_72481868087766_kernel(
    const float* __restrict__ img, float* __restrict__ out) {
    constexpr int W = 512, H = 512, PX = 4;
    const int tx = threadIdx.x;                  // 0..31
    const int ty = threadIdx.y;                  // 0..3
    const int x0 = (blockIdx.x * 32 + tx) * PX;  // 0..508
    const int y0 = (blockIdx.y * 4 + ty) * 2;    // 0..510 (even)
    const float* __restrict__ base = img + (size_t)blockIdx.z * (W * H);

    const bool left  = (x0 == 0);
    const bool right = (x0 == W - PX);

    // 8 real columns (x0-2 .. x0+5) folded into 6 packed columns:
    // c[j] = ( col[x0-2+j] , col[x0+j] )  -> lanes carry pixels (p, p+2).
    // 6 rows y0-2 .. y0+3 cover both output rows y0 and y0+1.
    __half2 c[6][6];
#pragma unroll
    for (int r = 0; r < 6; r++) {
        const int yy = y0 - 2 + r;
        const float* rp = ((unsigned)yy < (unsigned)H) ? (base + (size_t)yy * W) : g_zeros;
        const float4* qm = left  ? (const float4*)g_zeros : (const float4*)(rp + x0 - 4);
        const float4* qp = right ? (const float4*)g_zeros : (const float4*)(rp + x0 + 4);
        float4 v0 = __ldg(qm);
        float4 v1 = __ldg((const float4*)(rp + x0));
        float4 v2 = __ldg(qp);
        // reals: 0=v0.z(x-2) 1=v0.w 2=v1.x 3=v1.y 4=v1.z 5=v1.w 6=v2.x 7=v2.y(x+5)
        c[0][r] = __floats2half2_rn(v0.z, v1.x);
        c[1][r] = __floats2half2_rn(v0.w, v1.y);
        c[2][r] = __floats2half2_rn(v1.x, v1.z);
        c[3][r] = __floats2half2_rn(v1.y, v1.w);
        c[4][r] = __floats2half2_rn(v1.z, v2.x);
        c[5][r] = __floats2half2_rn(v1.w, v2.y);
    }

    // sort the shared quad (rows 1..4 = image rows y0-1..y0+2) in place
#pragma unroll
    for (int j = 0; j < 6; j++)
        sort4(c[j][1], c[j][2], c[j][3], c[j][4]);

    __half2 w[6][5];
    float res[PX];

    // ---- window A: rows y0-2..y0+2 (insert c[j][0]) -> output row y0 ----
#pragma unroll
    for (int j = 0; j < 6; j++)
        insert5(w[j], c[j][0], c[j][1], c[j][2], c[j][3], c[j][4]);
    {
        __half2 m0 = median25_cols(w[0], w[1], w[2], w[3], w[4]);  // px 0, 2
        __half2 m1 = median25_cols(w[1], w[2], w[3], w[4], w[5]);  // px 1, 3
        res[0] = __low2float(m0);  res[2] = __high2float(m0);
        res[1] = __low2float(m1);  res[3] = __high2float(m1);
#pragma unroll
        for (int p = 0; p < PX; p++) {
            const int x = x0 + p;
            const bool inter = (x >= 2) && (x < W - 2) && (y0 >= 2) && (y0 < H - 2);
            if (fabsf(res[p]) < 1.2e-4f && (inter || res[p] != 0.0f))
                res[p] = median25_fixup(base, x, y0);
        }
        *(float4*)(out + (size_t)blockIdx.z * (W * H) + (size_t)y0 * W + x0) =
            make_float4(res[0], res[1], res[2], res[3]);
    }

    // ---- window B: rows y0-1..y0+3 (insert c[j][5]) -> output row y0+1 ----
#pragma unroll
    for (int j = 0; j < 6; j++)
        insert5(w[j], c[j][5], c[j][1], c[j][2], c[j][3], c[j][4]);
    {
        __half2 m0 = median25_cols(w[0], w[1], w[2], w[3], w[4]);  // px 0, 2
        __half2 m1 = median25_cols(w[1], w[2], w[3], w[4], w[5]);  // px 1, 3
        res[0] = __low2float(m0);  res[2] = __high2float(m0);
        res[1] = __low2float(m1);  res[3] = __high2float(m1);
        const int y1 = y0 + 1;
#pragma unroll
        for (int p = 0; p < PX; p++) {
            const int x = x0 + p;
            const bool inter = (x >= 2) && (x < W - 2) && (y1 >= 2) && (y1 < H - 2);
            if (fabsf(res[p]) < 1.2e-4f && (inter || res[p] != 0.0f))
                res[p] = median25_fixup(base, x, y1);
        }
        *(float4*)(out + (size_t)blockIdx.z * (W * H) + (size_t)y1 * W + x0) =
            make_float4(res[0], res[1], res[2], res[3]);
    }
}

extern "C" void kernel_launch(void* const* d_in, const int* in_sizes, int n_in,
                              void* d_out, int out_size) {
    const float* img = (const float*)d_in[0];
    float* out = (float*)d_out;
    const int n_planes = in_sizes[0] / (512 * 512);  // 24
    dim3 blk(32, 4, 1);
    dim3 grd(512 / (32 * 4), 512 / (4 * 2), n_planes);  // (4, 64, 24)
    MedianBlur_72481868087766_kernel<<<grd, blk>>>(img, out);
}

// round 10
// speedup vs baseline: 1.1153x; 1.1153x over previous
#include <cuda_runtime.h>
#include <cuda_fp16.h>

// 5x5 median blur, zero padding, [N, 512, 512] fp32 planes (N = 24).
//
// fp16x2-packed EXACT compare-exchange network; each half2 lane pair carries
// pixels (p, p+4) of an 8-pixel strip. Every output equals some
// fp16-converted input (rel err <= 2^-11 for normal values); tiny medians
// (fp16 subnormal zone) are recomputed in fp32 under a rare predicate.
//
// R10: adjacent windows share 4 of 5 columns per matrix row -> group the 4
// median calls into 2 pairs; per row sort the shared quad once and extract
// each window's needed ranks with 3-6 instr merge-insertion formulas
// (selection cost -21%, values bit-identical to full row sorts).
//
// Selection pipeline (proved in earlier rounds):
//  both-sorted rank bound -> 13 candidates -> chain merges -> pruned
//  Batcher merge(5,5) -> median7 -> chain med5 formula.

__device__ __align__(16) float g_zeros[544];  // zero-initialized, never written

__device__ __forceinline__ float   vmn(float a, float b)     { return fminf(a, b); }
__device__ __forceinline__ float   vmx(float a, float b)     { return fmaxf(a, b); }
__device__ __forceinline__ __half2 vmn(__half2 a, __half2 b) { return __hmin2(a, b); }
__device__ __forceinline__ __half2 vmx(__half2 a, __half2 b) { return __hmax2(a, b); }

template <class T>
__device__ __forceinline__ void ce(T& a, T& b) {
    T t = vmn(a, b);
    b = vmx(a, b);
    a = t;
}

template <class T>
__device__ __forceinline__ void sort5(T& s0, T& s1, T& s2, T& s3, T& s4) {
    ce(s0, s1); ce(s2, s3); ce(s0, s2); ce(s1, s3); ce(s1, s2);
    ce(s3, s4); ce(s2, s3); ce(s1, s2); ce(s0, s1);
}

// sort4 (5 CE)
template <class T>
__device__ __forceinline__ void sort4(T& s1, T& s2, T& s3, T& s4) {
    ce(s1, s2); ce(s3, s4); ce(s1, s3); ce(s2, s4); ce(s2, s3);
}

// top2 of unsorted 4: mx = max, snd = 2nd max (7 instr)
template <class T>
__device__ __forceinline__ void top2of4(T x1, T x2, T x3, T x4, T& snd, T& mx) {
    T u1 = vmx(x1, x2), l1 = vmn(x1, x2);
    T u2 = vmx(x3, x4), l2 = vmn(x3, x4);
    mx  = vmx(u1, u2);
    snd = vmx(vmn(u1, u2), vmx(l1, l2));
}

// bot2 of unsorted 4: mn = min, snd = 2nd min (7 instr)
template <class T>
__device__ __forceinline__ void bot2of4(T x1, T x2, T x3, T x4, T& mn, T& snd) {
    T l1 = vmn(x1, x2), u1 = vmx(x1, x2);
    T l2 = vmn(x3, x4), u2 = vmx(x3, x4);
    mn  = vmn(l1, l2);
    snd = vmn(vmx(l1, l2), vmn(u1, u2));
}

// Median (rank 6) of the 13 both-sorted candidates:
// A<=Bv (row0 r3,r4), C<=D<=E (row1 r2..r4), F<=G<=Hh (row2 r1..r3),
// I<=J<=K (row3 r0..r2), L<=Mv (row4 r0,r1).
template <class T>
__device__ __forceinline__ T median13_tail(T A, T Bv, T C, T D, T E,
                                           T F, T G, T Hh, T I, T J, T K,
                                           T L, T Mv) {
    // chain merges -> sorted 5-chains Z=(A,D,Hh,Bv,E), X=(F,L,I,J,Mv)
    ce(D, Bv); ce(Hh, Bv); ce(Bv, E);
    ce(F, I);  ce(L, I);   ce(I, J);
    // pruned Batcher merge(5,5): middle four w3..w6 in e2,p2,e3,q2
    T p1 = vmx(F, A);
    T q1 = vmn(Mv, E);
    ce(p1, q1);
    ce(I, Hh);
    T e2 = vmx(p1, I);
    T e3 = vmn(q1, Hh);
    T p2 = vmx(L, D);
    T q2 = vmn(J, Bv);
    ce(p2, q2);
    ce(e2, p2);
    ce(e3, q2);
    // median13 = rank3 of {w3,w4,w5,w6, C,G,K}
    T t0 = vmx(e2, C);
    T t1 = vmn(q2, K);
    T t2 = G;
    ce(t0, t1); ce(t0, t2); ce(t1, t2);
    T m1 = vmx(p2, t0);
    T m2 = vmn(e3, t2);
    T lo = vmn(m1, m2), hi = vmx(m1, m2);
    return vmx(lo, vmn(hi, t1));
}

// Two medians for adjacent windows A=(c0..c4), B=(c1..c5); columns sorted.
// Shared middle quad per matrix row (c1..c4) sorted once; each window's
// ranks extracted via sorted-4+1 merge-insertion formulas.
template <class T>
__device__ __forceinline__ void median25_pair(const T* c0, const T* c1, const T* c2,
                                              const T* c3, const T* c4, const T* c5,
                                              T& mA, T& mB) {
    T AA, BA, CA, DA, EA, FA, GA, HA, IA, JA, KA, LA, MA;
    T AB, BB, CB, DB, EB, FB, GB, HB, IB, JB, KB, LB, MB;
    // row 0 (column minima): ranks 3,4
    {
        T s, m;
        top2of4(c1[0], c2[0], c3[0], c4[0], s, m);
        T e = c0[0];
        BA = vmx(m, e); AA = vmx(s, vmn(m, e));
        e = c5[0];
        BB = vmx(m, e); AB = vmx(s, vmn(m, e));
    }
    // row 1: ranks 2,3,4  (r2=min(b,q3), r3=min(c,q4), r4=max(c,q4))
    {
        T q1 = c1[1], q2 = c2[1], q3 = c3[1], q4 = c4[1];
        sort4(q1, q2, q3, q4);
        T e = c0[1];
        T a = vmx(e, q1), b = vmx(a, q2);
        CA = vmn(b, q3); T cc = vmx(b, q3); DA = vmn(cc, q4); EA = vmx(cc, q4);
        e = c5[1];
        a = vmx(e, q1); b = vmx(a, q2);
        CB = vmn(b, q3); cc = vmx(b, q3); DB = vmn(cc, q4); EB = vmx(cc, q4);
    }
    // row 2: ranks 1,2,3  (r1=min(a,q2), r2=min(b,q3), r3=min(c,q4))
    {
        T q1 = c1[2], q2 = c2[2], q3 = c3[2], q4 = c4[2];
        sort4(q1, q2, q3, q4);
        T e = c0[2];
        T a = vmx(e, q1);
        FA = vmn(a, q2); T b = vmx(a, q2);
        GA = vmn(b, q3); T cc = vmx(b, q3);
        HA = vmn(cc, q4);
        e = c5[2];
        a = vmx(e, q1);
        FB = vmn(a, q2); b = vmx(a, q2);
        GB = vmn(b, q3); cc = vmx(b, q3);
        HB = vmn(cc, q4);
    }
    // row 3: ranks 0,1,2  (r0=min(e,q1), r1=min(a,q2), r2=min(b,q3))
    {
        T q1 = c1[3], q2 = c2[3], q3 = c3[3], q4 = c4[3];
        sort4(q1, q2, q3, q4);
        T e = c0[3];
        IA = vmn(e, q1); T a = vmx(e, q1);
        JA = vmn(a, q2); T b = vmx(a, q2);
        KA = vmn(b, q3);
        e = c5[3];
        IB = vmn(e, q1); a = vmx(e, q1);
        JB = vmn(a, q2); b = vmx(a, q2);
        KB = vmn(b, q3);
    }
    // row 4 (column maxima): ranks 0,1
    {
        T mn, s;
        bot2of4(c1[4], c2[4], c3[4], c4[4], mn, s);
        T e = c0[4];
        LA = vmn(mn, e); MA = vmn(s, vmx(mn, e));
        e = c5[4];
        LB = vmn(mn, e); MB = vmn(s, vmx(mn, e));
    }
    mA = median13_tail(AA, BA, CA, DA, EA, FA, GA, HA, IA, JA, KA, LA, MA);
    mB = median13_tail(AB, BB, CB, DB, EB, FB, GB, HB, IB, JB, KB, LB, MB);
}

// Rare fp32 recompute for medians in the fp16 subnormal zone.
__device__ __noinline__ float median25_fixup(const float* __restrict__ base, int px, int py) {
    float c[5][5];
#pragma unroll
    for (int i = 0; i < 5; i++) {
        const int x = px - 2 + i;
        const bool xin = (unsigned)x < 512u;
#pragma unroll
        for (int r = 0; r < 5; r++) {
            const int yy = py - 2 + r;
            const bool in = xin && ((unsigned)yy < 512u);
            c[i][r] = in ? __ldg(base + (size_t)yy * 512 + x) : 0.0f;
        }
        sort5(c[i][0], c[i][1], c[i][2], c[i][3], c[i][4]);
    }
    float mA, mB;
    median25_pair(c[0], c[1], c[2], c[3], c[4], c[4], mA, mB);
    return mA;
}

__global__ __launch_bounds__(128) void MedianBlur_72481868087766_kernel(
    const float* __restrict__ img, float* __restrict__ out) {
    constexpr int W = 512, H = 512, PX = 8;
    const int tx = threadIdx.x;                  // 0..31
    const int ty = threadIdx.y;                  // 0..3
    const int x0 = (blockIdx.x * 32 + tx) * PX;  // 0..504
    const int y  = blockIdx.y * 4 + ty;
    const float* __restrict__ base = img + (size_t)blockIdx.z * (W * H);

    const bool left  = (x0 == 0);
    const bool right = (x0 == W - PX);

    // 12 real columns (x0-2 .. x0+9) folded into 8 packed columns:
    // pc[j] = ( col[x0-2+j] , col[x0+2+j] )  -> lanes carry pixels (p, p+4)
    __half2 pc[8][5];
#pragma unroll
    for (int r = 0; r < 5; r++) {
        const int yy = y - 2 + r;
        const float* rp = ((unsigned)yy < (unsigned)H) ? (base + (size_t)yy * W) : g_zeros;
        const float4* qm = left  ? (const float4*)g_zeros : (const float4*)(rp + x0 - 4);
        const float4* qp = right ? (const float4*)g_zeros : (const float4*)(rp + x0 + 8);
        float4 v0 = __ldg(qm);
        float4 v1 = __ldg((const float4*)(rp + x0));
        float4 v2 = __ldg((const float4*)(rp + x0 + 4));
        float4 v3 = __ldg(qp);
        pc[0][r] = __floats2half2_rn(v0.z, v1.z);
        pc[1][r] = __floats2half2_rn(v0.w, v1.w);
        pc[2][r] = __floats2half2_rn(v1.x, v2.x);
        pc[3][r] = __floats2half2_rn(v1.y, v2.y);
        pc[4][r] = __floats2half2_rn(v1.z, v2.z);
        pc[5][r] = __floats2half2_rn(v1.w, v2.w);
        pc[6][r] = __floats2half2_rn(v2.x, v3.x);
        pc[7][r] = __floats2half2_rn(v2.y, v3.y);
    }

    // sort packed columns (shared across the 8 output pixels)
#pragma unroll
    for (int j = 0; j < 8; j++)
        sort5(pc[j][0], pc[j][1], pc[j][2], pc[j][3], pc[j][4]);

    // paired selection: (W0,W1) share pc1-4; (W2,W3) share pc3-6
    __half2 m0, m1, m2, m3;
    median25_pair(pc[0], pc[1], pc[2], pc[3], pc[4], pc[5], m0, m1);
    median25_pair(pc[2], pc[3], pc[4], pc[5], pc[6], pc[7], m2, m3);

    float res[PX];
    res[0] = __low2float(m0);  res[4] = __high2float(m0);
    res[1] = __low2float(m1);  res[5] = __high2float(m1);
    res[2] = __low2float(m2);  res[6] = __high2float(m2);
    res[3] = __low2float(m3);  res[7] = __high2float(m3);

    // fp32 fixup for medians in the fp16 subnormal zone. Exact zeros at the
    // 2-pixel border ring come from zero padding and are exact in fp16.
#pragma unroll
    for (int p = 0; p < PX; p++) {
        const int x = x0 + p;
        const bool inter = (x >= 2) && (x < W - 2) && (y >= 2) && (y < H - 2);
        if (fabsf(res[p]) < 1.2e-4f && (inter || res[p] != 0.0f))
            res[p] = median25_fixup(base, x, y);
    }

    float4* o = (float4*)(out + (size_t)blockIdx.z * (W * H) + (size_t)y * W + x0);
    o[0] = make_float4(res[0], res[1], res[2], res[3]);
    o[1] = make_float4(res[4], res[5], res[6], res[7]);
}

extern "C" void kernel_launch(void* const* d_in, const int* in_sizes, int n_in,
                              void* d_out, int out_size) {
    const float* img = (const float*)d_in[0];
    float* out = (float*)d_out;
    const int n_planes = in_sizes[0] / (512 * 512);  // 24
    dim3 blk(32, 4, 1);
    dim3 grd(512 / (32 * 8), 512 / 4, n_planes);     // (2, 128, 24)
    MedianBlur_72481868087766_kernel<<<grd, blk>>>(img, out);
}